// round 10
// baseline (speedup 1.0000x reference)
#include <cuda_runtime.h>
#include <cstdint>

#define NB   4
#define NH   16
#define SEQ  2048
#define DMOD 1024
#define DH   64
#define BHN  (NB * NH)        // 64
#define SL   4194304          // floats per attn slice (2048*2048)
#define PBH  131072           // floats per (bh) Q/K/V slab (2048*64)
#define NSPLIT 58             // bh 0..57 staged in d_out, 58..63 in g_tail

// Scratch: 6 tail (bh) Q/K/V slabs (9.4 MB) + row sums (0.5 MB).
static __device__ float g_tail[18 * PBH];
static __device__ float g_sums[(size_t)BHN * SEQ];

// ---------------------------------------------------------------------------
// tf32 helpers
// ---------------------------------------------------------------------------
__device__ __forceinline__ uint32_t f2tf(float f) {
    uint32_t u;
    asm("cvt.rna.tf32.f32 %0, %1;" : "=r"(u) : "f"(f));
    return u;
}

__device__ __forceinline__ void mma_tf32(float* c, const uint32_t* a, const uint32_t* b) {
    asm volatile(
        "mma.sync.aligned.m16n8k8.row.col.f32.tf32.tf32.f32 "
        "{%0,%1,%2,%3}, {%4,%5,%6,%7}, {%8,%9}, {%0,%1,%2,%3};"
        : "+f"(c[0]), "+f"(c[1]), "+f"(c[2]), "+f"(c[3])
        : "r"(a[0]), "r"(a[1]), "r"(a[2]), "r"(a[3]), "r"(b[0]), "r"(b[1]));
}

// ---------------------------------------------------------------------------
// Kernel 1: fused QKV projection via tf32 mma (validated; unchanged).
// ---------------------------------------------------------------------------
__global__ __launch_bounds__(256) void proj_kernel(
    const float* __restrict__ xq, const float* __restrict__ xk, const float* __restrict__ xv,
    const float* __restrict__ wq, const float* __restrict__ wk, const float* __restrict__ wv,
    const float* __restrict__ bq, const float* __restrict__ bk, const float* __restrict__ bv,
    float* __restrict__ stage)
{
    const int which = blockIdx.z;
    const float* X  = (which == 0) ? xq : (which == 1) ? xk : xv;
    const float* W  = (which == 0) ? wq : (which == 1) ? wk : wv;
    const float* Bi = (which == 0) ? bq : (which == 1) ? bk : bv;

    __shared__ uint32_t As[16][136];
    __shared__ uint32_t Bs[16][136];

    const int tid  = threadIdx.x;
    const int warp = tid >> 5;
    const int lane = tid & 31;
    const int gr   = lane >> 2;
    const int tg   = lane & 3;

    const int m0 = blockIdx.y * 128;
    const int n0 = blockIdx.x * 128;
    const int warp_m = (warp >> 2) * 64;
    const int warp_n = (warp & 3) * 32;

    const int a_r = tid >> 1;
    const int a_kc = (tid & 1) * 8;
    const int b_kr = tid >> 4;
    const int b_nc = (tid & 15) * 8;

    float acc[4][4][4];
#pragma unroll
    for (int mt = 0; mt < 4; mt++)
#pragma unroll
        for (int nt = 0; nt < 4; nt++)
#pragma unroll
            for (int r = 0; r < 4; r++) acc[mt][nt][r] = 0.f;

    for (int k0 = 0; k0 < DMOD; k0 += 16) {
        float4 x0 = *(const float4*)&X[(size_t)(m0 + a_r) * DMOD + k0 + a_kc];
        float4 x1 = *(const float4*)&X[(size_t)(m0 + a_r) * DMOD + k0 + a_kc + 4];
        float4 w0 = *(const float4*)&W[(size_t)(k0 + b_kr) * DMOD + n0 + b_nc];
        float4 w1 = *(const float4*)&W[(size_t)(k0 + b_kr) * DMOD + n0 + b_nc + 4];
        __syncthreads();
        As[a_kc + 0][a_r] = f2tf(x0.x);
        As[a_kc + 1][a_r] = f2tf(x0.y);
        As[a_kc + 2][a_r] = f2tf(x0.z);
        As[a_kc + 3][a_r] = f2tf(x0.w);
        As[a_kc + 4][a_r] = f2tf(x1.x);
        As[a_kc + 5][a_r] = f2tf(x1.y);
        As[a_kc + 6][a_r] = f2tf(x1.z);
        As[a_kc + 7][a_r] = f2tf(x1.w);
        Bs[b_kr][b_nc + 0] = f2tf(w0.x);
        Bs[b_kr][b_nc + 1] = f2tf(w0.y);
        Bs[b_kr][b_nc + 2] = f2tf(w0.z);
        Bs[b_kr][b_nc + 3] = f2tf(w0.w);
        Bs[b_kr][b_nc + 4] = f2tf(w1.x);
        Bs[b_kr][b_nc + 5] = f2tf(w1.y);
        Bs[b_kr][b_nc + 6] = f2tf(w1.z);
        Bs[b_kr][b_nc + 7] = f2tf(w1.w);
        __syncthreads();

#pragma unroll
        for (int kk = 0; kk < 16; kk += 8) {
            uint32_t af[4][4], bf[4][2];
#pragma unroll
            for (int mt = 0; mt < 4; mt++) {
                const int mm = warp_m + mt * 16 + gr;
                af[mt][0] = As[kk + tg][mm];
                af[mt][1] = As[kk + tg][mm + 8];
                af[mt][2] = As[kk + tg + 4][mm];
                af[mt][3] = As[kk + tg + 4][mm + 8];
            }
#pragma unroll
            for (int nt = 0; nt < 4; nt++) {
                const int nn = warp_n + nt * 8 + gr;
                bf[nt][0] = Bs[kk + tg][nn];
                bf[nt][1] = Bs[kk + tg + 4][nn];
            }
#pragma unroll
            for (int mt = 0; mt < 4; mt++)
#pragma unroll
                for (int nt = 0; nt < 4; nt++)
                    mma_tf32(acc[mt][nt], af[mt], bf[nt]);
        }
    }

    const int h  = (n0 + warp_n) >> 6;
    const int bb = m0 >> 11;
    const int bh = bb * NH + h;
    const int d_base = ((n0 + warp_n) & 63);
    const int ss_base = (m0 & (SEQ - 1)) + warp_m;

    float* dst = (bh < NSPLIT)
        ? stage + (size_t)which * 8388608 + (size_t)bh * PBH
        : g_tail + (size_t)which * (6 * PBH) + (size_t)(bh - NSPLIT) * PBH;

#pragma unroll
    for (int nt = 0; nt < 4; nt++) {
        const int ncol = n0 + warp_n + nt * 8 + 2 * tg;
        const float bias0 = Bi[ncol];
        const float bias1 = Bi[ncol + 1];
        const int d = d_base + nt * 8 + 2 * tg;
#pragma unroll
        for (int mt = 0; mt < 4; mt++) {
            const int s0 = ss_base + mt * 16 + gr;
            float2 v0 = make_float2(acc[mt][nt][0] + bias0, acc[mt][nt][1] + bias1);
            float2 v1 = make_float2(acc[mt][nt][2] + bias0, acc[mt][nt][3] + bias1);
            *(float2*)&dst[(size_t)s0 * DH + d] = v0;
            *(float2*)&dst[(size_t)(s0 + 8) * DH + d] = v1;
        }
    }
}

// ---------------------------------------------------------------------------
// Kernel 2: FUSED attention, occupancy-optimized.
// Per block: one bh, 64 q-rows. 8 warps = 4 row-groups x 2 key-halves.
// Warp (rg, kg): q-rows rg*16..+15, keys kg*64..+63 of each 128-key tile.
// S = QK^T/8 (masked) -> p = exp(S) -> attn (unnormalized) + rowsum;
// ctx = (p @ V) * inv_sum with cross-kg reduction at epilogue.
// smem: Qs[64][68] | Ks[128][68] | Vs[128][72] = 87 KB -> 2 blocks/SM.
// ---------------------------------------------------------------------------
#define QS_STRIDE 68
#define VS_STRIDE 72
#define QROWS 64
#define SMEM_WORDS (QROWS * QS_STRIDE + 128 * QS_STRIDE + 128 * VS_STRIDE)

__global__ __launch_bounds__(256, 2) void fused_attn_kernel(
    const unsigned char* __restrict__ mask, float* __restrict__ attn,
    float* __restrict__ ctx, const float* __restrict__ stage, int bh0)
{
    extern __shared__ uint32_t smem[];
    uint32_t* Qs = smem;                        // [64][68]
    uint32_t* Ks = smem + QROWS * QS_STRIDE;    // [128][68]
    uint32_t* Vs = Ks + 128 * QS_STRIDE;        // [128][72]

    const int bh = bh0 + blockIdx.y;
    const int m0 = blockIdx.x * QROWS;
    const int b = bh >> 4, h = bh & 15;

    const float* Q = (bh < NSPLIT)
        ? stage + (size_t)bh * PBH
        : g_tail + (size_t)(bh - NSPLIT) * PBH;
    const float* K = (bh < NSPLIT)
        ? stage + 8388608 + (size_t)bh * PBH
        : g_tail + (size_t)(6 * PBH) + (size_t)(bh - NSPLIT) * PBH;
    const float* V = (bh < NSPLIT)
        ? stage + 16777216 + (size_t)bh * PBH
        : g_tail + (size_t)(12 * PBH) + (size_t)(bh - NSPLIT) * PBH;

    const int tid  = threadIdx.x;
    const int warp = tid >> 5;
    const int lane = tid & 31;
    const int gr   = lane >> 2;
    const int tg   = lane & 3;
    const int rg   = warp & 3;       // row group 0..3
    const int kg   = warp >> 2;      // key half 0..1

    const int r0 = rg * 16 + gr;     // q-row (local, 0..63)
    const int r1 = r0 + 8;

    // --- stage Q into smem (tf32): 64 rows x 64 cols ---
    {
        const int qrow = tid >> 2;             // 0..63
        const int kc   = (tid & 3) * 16;       // 0,16,32,48
        const float* src = Q + (size_t)(m0 + qrow) * DH + kc;
#pragma unroll
        for (int i = 0; i < 4; i++) {
            float4 v = *(const float4*)&src[i * 4];
            uint4 u = make_uint4(f2tf(v.x), f2tf(v.y), f2tf(v.z), f2tf(v.w));
            *(uint4*)&Qs[qrow * QS_STRIDE + kc + i * 4] = u;
        }
    }
    __syncthreads();

    // --- preload Q A-fragments: qf[8 k-chunks][4] ---
    uint32_t qf[8][4];
#pragma unroll
    for (int kc = 0; kc < 8; kc++) {
        qf[kc][0] = Qs[r0 * QS_STRIDE + kc * 8 + tg];
        qf[kc][1] = Qs[r1 * QS_STRIDE + kc * 8 + tg];
        qf[kc][2] = Qs[r0 * QS_STRIDE + kc * 8 + tg + 4];
        qf[kc][3] = Qs[r1 * QS_STRIDE + kc * 8 + tg + 4];
    }

    float rsum0 = 0.f, rsum1 = 0.f;
    float ctxacc[8][4];
#pragma unroll
    for (int dt = 0; dt < 8; dt++)
#pragma unroll
        for (int r = 0; r < 4; r++) ctxacc[dt][r] = 0.f;

    const unsigned char* mrow0 = mask + ((size_t)b * SEQ + m0 + r0) * SEQ;
    const unsigned char* mrow1 = mask + ((size_t)b * SEQ + m0 + r1) * SEQ;
    float* arow0 = attn + ((size_t)bh * SEQ + m0 + r0) * SEQ;
    float* arow1 = attn + ((size_t)bh * SEQ + m0 + r1) * SEQ;

    const int ld_key = tid >> 1;
    const int ld_kc  = (tid & 1) * 32;
    const int quad   = lane & ~3;
    const int kbase  = kg * 64;           // this warp's key offset in tile

    for (int kt = 0; kt < 16; kt++) {
        // --- load K,V tiles (tf32): 128 keys x 64 dims each ---
        {
            const float* ksrc = K + (size_t)(kt * 128 + ld_key) * DH + ld_kc;
            const float* vsrc = V + (size_t)(kt * 128 + ld_key) * DH + ld_kc;
#pragma unroll
            for (int i = 0; i < 8; i++) {
                float4 kv = *(const float4*)&ksrc[i * 4];
                *(uint4*)&Ks[ld_key * QS_STRIDE + ld_kc + i * 4] =
                    make_uint4(f2tf(kv.x), f2tf(kv.y), f2tf(kv.z), f2tf(kv.w));
                float4 vv = *(const float4*)&vsrc[i * 4];
                *(uint4*)&Vs[ld_key * VS_STRIDE + ld_kc + i * 4] =
                    make_uint4(f2tf(vv.x), f2tf(vv.y), f2tf(vv.z), f2tf(vv.w));
            }
        }
        __syncthreads();

        // --- S = Q K^T for this warp's 16x64 sub-tile ---
        float sacc[8][4];
#pragma unroll
        for (int nt = 0; nt < 8; nt++)
#pragma unroll
            for (int r = 0; r < 4; r++) sacc[nt][r] = 0.f;

#pragma unroll
        for (int kc = 0; kc < 8; kc++) {
#pragma unroll
            for (int nt = 0; nt < 8; nt++) {
                uint32_t bf[2];
                bf[0] = Ks[(kbase + nt * 8 + gr) * QS_STRIDE + kc * 8 + tg];
                bf[1] = Ks[(kbase + nt * 8 + gr) * QS_STRIDE + kc * 8 + tg + 4];
                mma_tf32(sacc[nt], qf[kc], bf);
            }
        }

        // --- scale, mask, exp, rowsum, write unnormalized p ---
        const int colb = kt * 128 + kbase;
#pragma unroll
        for (int nt = 0; nt < 8; nt++) {
            const int col = colb + nt * 8 + 2 * tg;
            uchar2 mm0 = *(const uchar2*)&mrow0[col];
            uchar2 mm1 = *(const uchar2*)&mrow1[col];
            float s00 = mm0.x ? -1e9f : sacc[nt][0] * 0.125f;
            float s01 = mm0.y ? -1e9f : sacc[nt][1] * 0.125f;
            float s10 = mm1.x ? -1e9f : sacc[nt][2] * 0.125f;
            float s11 = mm1.y ? -1e9f : sacc[nt][3] * 0.125f;
            float p00 = __expf(s00), p01 = __expf(s01);
            float p10 = __expf(s10), p11 = __expf(s11);
            rsum0 += p00 + p01;
            rsum1 += p10 + p11;
            sacc[nt][0] = p00; sacc[nt][1] = p01;
            sacc[nt][2] = p10; sacc[nt][3] = p11;
            *(float2*)&arow0[col] = make_float2(p00, p01);
            *(float2*)&arow1[col] = make_float2(p10, p11);
        }

        // --- ctx += p @ V over this warp's 64 keys (quad-shfl routing) ---
#pragma unroll
        for (int kc = 0; kc < 8; kc++) {
            const int srcA = quad + (tg >> 1);
            const int srcB = srcA + 2;
            float x0 = __shfl_sync(0xffffffffu, sacc[kc][0], srcA);
            float x1 = __shfl_sync(0xffffffffu, sacc[kc][1], srcA);
            float y0 = __shfl_sync(0xffffffffu, sacc[kc][0], srcB);
            float y1 = __shfl_sync(0xffffffffu, sacc[kc][1], srcB);
            float z0 = __shfl_sync(0xffffffffu, sacc[kc][2], srcA);
            float z1 = __shfl_sync(0xffffffffu, sacc[kc][3], srcA);
            float w0 = __shfl_sync(0xffffffffu, sacc[kc][2], srcB);
            float w1 = __shfl_sync(0xffffffffu, sacc[kc][3], srcB);
            uint32_t pa[4];
            pa[0] = f2tf((tg & 1) ? x1 : x0);
            pa[1] = f2tf((tg & 1) ? z1 : z0);
            pa[2] = f2tf((tg & 1) ? y1 : y0);
            pa[3] = f2tf((tg & 1) ? w1 : w0);
#pragma unroll
            for (int dt = 0; dt < 8; dt++) {
                uint32_t vb[2];
                vb[0] = Vs[(kbase + kc * 8 + tg) * VS_STRIDE + dt * 8 + gr];
                vb[1] = Vs[(kbase + kc * 8 + tg + 4) * VS_STRIDE + dt * 8 + gr];
                mma_tf32(ctxacc[dt], pa, vb);
            }
        }
        __syncthreads();
    }

    // --- cross-kg reduction: kg=1 stores partials, kg=0 adds & writes ---
    float* buf = (float*)smem;   // Qs/Ks regions are dead now
    __syncthreads();
    if (kg == 1) {
        const int base = (rg * 32 + lane) * 36;
#pragma unroll
        for (int dt = 0; dt < 8; dt++)
#pragma unroll
            for (int r = 0; r < 4; r++) buf[base + dt * 4 + r] = ctxacc[dt][r];
        buf[base + 32] = rsum0;
        buf[base + 33] = rsum1;
    }
    __syncthreads();
    if (kg == 0) {
        const int base = (rg * 32 + lane) * 36;
#pragma unroll
        for (int dt = 0; dt < 8; dt++)
#pragma unroll
            for (int r = 0; r < 4; r++) ctxacc[dt][r] += buf[base + dt * 4 + r];
        rsum0 += buf[base + 32];
        rsum1 += buf[base + 33];

        // full row sums via quad reduce
        rsum0 += __shfl_xor_sync(0xffffffffu, rsum0, 1);
        rsum0 += __shfl_xor_sync(0xffffffffu, rsum0, 2);
        rsum1 += __shfl_xor_sync(0xffffffffu, rsum1, 1);
        rsum1 += __shfl_xor_sync(0xffffffffu, rsum1, 2);
        if (tg == 0) {
            g_sums[(size_t)bh * SEQ + m0 + r0] = rsum0;
            g_sums[(size_t)bh * SEQ + m0 + r1] = rsum1;
        }
        const float inv0 = 1.0f / rsum0;
        const float inv1 = 1.0f / rsum1;

        float* crow0 = ctx + ((size_t)b * SEQ + m0 + r0) * DMOD + h * DH;
        float* crow1 = ctx + ((size_t)b * SEQ + m0 + r1) * DMOD + h * DH;
#pragma unroll
        for (int dt = 0; dt < 8; dt++) {
            const int d = dt * 8 + 2 * tg;
            *(float2*)&crow0[d] = make_float2(ctxacc[dt][0] * inv0, ctxacc[dt][1] * inv0);
            *(float2*)&crow1[d] = make_float2(ctxacc[dt][2] * inv1, ctxacc[dt][3] * inv1);
        }
    }
}

// ---------------------------------------------------------------------------
// Kernel 3: scale attn rows by 1/rowsum (at DRAM roofline; unchanged).
// ---------------------------------------------------------------------------
__global__ __launch_bounds__(256) void scale_kernel(float* __restrict__ attn)
{
    const size_t row = blockIdx.x;
    const float inv = 1.0f / g_sums[row];
    float* p = attn + row * SEQ;
    const int tid = threadIdx.x;
    float4 v0 = *(float4*)&p[tid * 4];
    float4 v1 = *(float4*)&p[1024 + tid * 4];
    v0.x *= inv; v0.y *= inv; v0.z *= inv; v0.w *= inv;
    v1.x *= inv; v1.y *= inv; v1.z *= inv; v1.w *= inv;
    *(float4*)&p[tid * 4] = v0;
    *(float4*)&p[1024 + tid * 4] = v1;
}

// ---------------------------------------------------------------------------
// Launch. Output: [context (4,2048,1024) | attn (4,16,2048,2048)] fp32.
// Q/K/V for bh<58 staged in attn slices 58..63; bh>=58 in g_tail.
// ---------------------------------------------------------------------------
extern "C" void kernel_launch(void* const* d_in, const int* in_sizes, int n_in,
                              void* d_out, int out_size)
{
    (void)in_sizes; (void)n_in; (void)out_size;
    const float* q  = (const float*)d_in[0];
    const float* k  = (const float*)d_in[1];
    const float* v  = (const float*)d_in[2];
    const unsigned char* mask = (const unsigned char*)d_in[3];
    const float* wq = (const float*)d_in[4];
    const float* wk = (const float*)d_in[5];
    const float* wv = (const float*)d_in[6];
    const float* bq = (const float*)d_in[7];
    const float* bk = (const float*)d_in[8];
    const float* bv = (const float*)d_in[9];

    float* ctx   = (float*)d_out;
    float* attn  = (float*)d_out + (size_t)NB * SEQ * DMOD;
    float* stage = attn + (size_t)NSPLIT * SL;

    const int smem_bytes = SMEM_WORDS * 4;   // 89088 B -> 2 blocks/SM
    cudaFuncSetAttribute(fused_attn_kernel,
                         cudaFuncAttributeMaxDynamicSharedMemorySize, smem_bytes);

    // 1) QKV projections into staging
    {
        dim3 grid(DMOD / 128, (NB * SEQ) / 128, 3);
        proj_kernel<<<grid, 256>>>(q, k, v, wq, wk, wv, bq, bk, bv, stage);
    }
    // 2) Phase A: fused attention for bh 0..57
    {
        dim3 grid(SEQ / QROWS, NSPLIT);
        fused_attn_kernel<<<grid, 256, smem_bytes>>>(mask, attn, ctx, stage, 0);
    }
    // 3) Phase B: fused attention for bh 58..63 (QKV in g_tail)
    {
        dim3 grid(SEQ / QROWS, BHN - NSPLIT);
        fused_attn_kernel<<<grid, 256, smem_bytes>>>(mask, attn, ctx, stage, NSPLIT);
    }
    // 4) Normalize the attn output
    scale_kernel<<<BHN * SEQ, 256>>>(attn);
}

// round 11
// speedup vs baseline: 1.2547x; 1.2547x over previous
#include <cuda_runtime.h>
#include <cuda_fp16.h>
#include <cstdint>

#define NB   4
#define NH   16
#define SEQ  2048
#define DMOD 1024
#define DH   64
#define BHN  (NB * NH)        // 64
#define SL   4194304          // floats per attn slice (2048*2048)
#define PBH  131072           // floats per (bh) Q/K/V slab (2048*64)
#define NSPLIT 58             // bh 0..57 staged in d_out, 58..63 in g_tail

// Scratch: 6 tail (bh) Q/K/V slabs (9.4 MB) + row sums (0.5 MB).
static __device__ float g_tail[18 * PBH];
static __device__ float g_sums[(size_t)BHN * SEQ];

// ---------------------------------------------------------------------------
// helpers
// ---------------------------------------------------------------------------
__device__ __forceinline__ uint32_t f2tf(float f) {
    uint32_t u;
    asm("cvt.rna.tf32.f32 %0, %1;" : "=r"(u) : "f"(f));
    return u;
}

__device__ __forceinline__ uint32_t pack_h2(float lo, float hi) {
    __half2 h = __floats2half2_rn(lo, hi);
    return *reinterpret_cast<uint32_t*>(&h);
}

__device__ __forceinline__ void mma_tf32(float* c, const uint32_t* a, const uint32_t* b) {
    asm volatile(
        "mma.sync.aligned.m16n8k8.row.col.f32.tf32.tf32.f32 "
        "{%0,%1,%2,%3}, {%4,%5,%6,%7}, {%8,%9}, {%0,%1,%2,%3};"
        : "+f"(c[0]), "+f"(c[1]), "+f"(c[2]), "+f"(c[3])
        : "r"(a[0]), "r"(a[1]), "r"(a[2]), "r"(a[3]), "r"(b[0]), "r"(b[1]));
}

__device__ __forceinline__ void mma_f16(float* c, const uint32_t* a, const uint32_t* b) {
    asm volatile(
        "mma.sync.aligned.m16n8k16.row.col.f32.f16.f16.f32 "
        "{%0,%1,%2,%3}, {%4,%5,%6,%7}, {%8,%9}, {%0,%1,%2,%3};"
        : "+f"(c[0]), "+f"(c[1]), "+f"(c[2]), "+f"(c[3])
        : "r"(a[0]), "r"(a[1]), "r"(a[2]), "r"(a[3]), "r"(b[0]), "r"(b[1]));
}

// ---------------------------------------------------------------------------
// Kernel 1: fused QKV projection via tf32 mma (validated; unchanged).
// ---------------------------------------------------------------------------
__global__ __launch_bounds__(256) void proj_kernel(
    const float* __restrict__ xq, const float* __restrict__ xk, const float* __restrict__ xv,
    const float* __restrict__ wq, const float* __restrict__ wk, const float* __restrict__ wv,
    const float* __restrict__ bq, const float* __restrict__ bk, const float* __restrict__ bv,
    float* __restrict__ stage)
{
    const int which = blockIdx.z;
    const float* X  = (which == 0) ? xq : (which == 1) ? xk : xv;
    const float* W  = (which == 0) ? wq : (which == 1) ? wk : wv;
    const float* Bi = (which == 0) ? bq : (which == 1) ? bk : bv;

    __shared__ uint32_t As[16][136];
    __shared__ uint32_t Bs[16][136];

    const int tid  = threadIdx.x;
    const int warp = tid >> 5;
    const int lane = tid & 31;
    const int gr   = lane >> 2;
    const int tg   = lane & 3;

    const int m0 = blockIdx.y * 128;
    const int n0 = blockIdx.x * 128;
    const int warp_m = (warp >> 2) * 64;
    const int warp_n = (warp & 3) * 32;

    const int a_r = tid >> 1;
    const int a_kc = (tid & 1) * 8;
    const int b_kr = tid >> 4;
    const int b_nc = (tid & 15) * 8;

    float acc[4][4][4];
#pragma unroll
    for (int mt = 0; mt < 4; mt++)
#pragma unroll
        for (int nt = 0; nt < 4; nt++)
#pragma unroll
            for (int r = 0; r < 4; r++) acc[mt][nt][r] = 0.f;

    for (int k0 = 0; k0 < DMOD; k0 += 16) {
        float4 x0 = *(const float4*)&X[(size_t)(m0 + a_r) * DMOD + k0 + a_kc];
        float4 x1 = *(const float4*)&X[(size_t)(m0 + a_r) * DMOD + k0 + a_kc + 4];
        float4 w0 = *(const float4*)&W[(size_t)(k0 + b_kr) * DMOD + n0 + b_nc];
        float4 w1 = *(const float4*)&W[(size_t)(k0 + b_kr) * DMOD + n0 + b_nc + 4];
        __syncthreads();
        As[a_kc + 0][a_r] = f2tf(x0.x);
        As[a_kc + 1][a_r] = f2tf(x0.y);
        As[a_kc + 2][a_r] = f2tf(x0.z);
        As[a_kc + 3][a_r] = f2tf(x0.w);
        As[a_kc + 4][a_r] = f2tf(x1.x);
        As[a_kc + 5][a_r] = f2tf(x1.y);
        As[a_kc + 6][a_r] = f2tf(x1.z);
        As[a_kc + 7][a_r] = f2tf(x1.w);
        Bs[b_kr][b_nc + 0] = f2tf(w0.x);
        Bs[b_kr][b_nc + 1] = f2tf(w0.y);
        Bs[b_kr][b_nc + 2] = f2tf(w0.z);
        Bs[b_kr][b_nc + 3] = f2tf(w0.w);
        Bs[b_kr][b_nc + 4] = f2tf(w1.x);
        Bs[b_kr][b_nc + 5] = f2tf(w1.y);
        Bs[b_kr][b_nc + 6] = f2tf(w1.z);
        Bs[b_kr][b_nc + 7] = f2tf(w1.w);
        __syncthreads();

#pragma unroll
        for (int kk = 0; kk < 16; kk += 8) {
            uint32_t af[4][4], bf[4][2];
#pragma unroll
            for (int mt = 0; mt < 4; mt++) {
                const int mm = warp_m + mt * 16 + gr;
                af[mt][0] = As[kk + tg][mm];
                af[mt][1] = As[kk + tg][mm + 8];
                af[mt][2] = As[kk + tg + 4][mm];
                af[mt][3] = As[kk + tg + 4][mm + 8];
            }
#pragma unroll
            for (int nt = 0; nt < 4; nt++) {
                const int nn = warp_n + nt * 8 + gr;
                bf[nt][0] = Bs[kk + tg][nn];
                bf[nt][1] = Bs[kk + tg + 4][nn];
            }
#pragma unroll
            for (int mt = 0; mt < 4; mt++)
#pragma unroll
                for (int nt = 0; nt < 4; nt++)
                    mma_tf32(acc[mt][nt], af[mt], bf[nt]);
        }
    }

    const int h  = (n0 + warp_n) >> 6;
    const int bb = m0 >> 11;
    const int bh = bb * NH + h;
    const int d_base = ((n0 + warp_n) & 63);
    const int ss_base = (m0 & (SEQ - 1)) + warp_m;

    float* dst = (bh < NSPLIT)
        ? stage + (size_t)which * 8388608 + (size_t)bh * PBH
        : g_tail + (size_t)which * (6 * PBH) + (size_t)(bh - NSPLIT) * PBH;

#pragma unroll
    for (int nt = 0; nt < 4; nt++) {
        const int ncol = n0 + warp_n + nt * 8 + 2 * tg;
        const float bias0 = Bi[ncol];
        const float bias1 = Bi[ncol + 1];
        const int d = d_base + nt * 8 + 2 * tg;
#pragma unroll
        for (int mt = 0; mt < 4; mt++) {
            const int s0 = ss_base + mt * 16 + gr;
            float2 v0 = make_float2(acc[mt][nt][0] + bias0, acc[mt][nt][1] + bias1);
            float2 v1 = make_float2(acc[mt][nt][2] + bias0, acc[mt][nt][3] + bias1);
            *(float2*)&dst[(size_t)s0 * DH + d] = v0;
            *(float2*)&dst[(size_t)(s0 + 8) * DH + d] = v1;
        }
    }
}

// ---------------------------------------------------------------------------
// Kernel 2: FUSED attention (R9 structure + fp16 PV via FA2 fragment reuse).
// Per block: one bh, 128 q-rows; warp w owns rows w*16..+15, all 128 keys/tile.
// S = QK^T (tf32) -> p = exp(S/8 masked) in fp32 -> attn write + rowsum;
// PV in fp16 m16n8k16: S C-frags pack IN-THREAD into A-frags (no shuffles),
// V stored in smem as half2 key-pairs matching the B-fragment layout.
// smem: Qs[128][68] tf32 | Ks[128][68] tf32 | Vhs[64][72] half2 = 88 KB.
// ---------------------------------------------------------------------------
#define QS_STRIDE 68
#define VH_STRIDE 72
#define SMEM_WORDS (2 * 128 * QS_STRIDE + 64 * VH_STRIDE)

__global__ __launch_bounds__(256) void fused_attn_kernel(
    const unsigned char* __restrict__ mask, float* __restrict__ attn,
    float* __restrict__ ctx, const float* __restrict__ stage, int bh0)
{
    extern __shared__ uint32_t smem[];
    uint32_t* Qs  = smem;                        // [128][68] tf32
    uint32_t* Ks  = smem + 128 * QS_STRIDE;      // [128][68] tf32
    uint32_t* Vhs = Ks + 128 * QS_STRIDE;        // [64][72] half2 (keys 2r,2r+1)

    const int bh = bh0 + blockIdx.y;
    const int m0 = blockIdx.x * 128;
    const int b = bh >> 4, h = bh & 15;

    const float* Q = (bh < NSPLIT)
        ? stage + (size_t)bh * PBH
        : g_tail + (size_t)(bh - NSPLIT) * PBH;
    const float* K = (bh < NSPLIT)
        ? stage + 8388608 + (size_t)bh * PBH
        : g_tail + (size_t)(6 * PBH) + (size_t)(bh - NSPLIT) * PBH;
    const float* V = (bh < NSPLIT)
        ? stage + 16777216 + (size_t)bh * PBH
        : g_tail + (size_t)(12 * PBH) + (size_t)(bh - NSPLIT) * PBH;

    const int tid  = threadIdx.x;
    const int warp = tid >> 5;
    const int lane = tid & 31;
    const int gr   = lane >> 2;
    const int tg   = lane & 3;

    const int r0 = warp * 16 + gr;
    const int r1 = r0 + 8;

    // --- stage Q into smem (tf32) ---
    {
        const int qrow = tid >> 1;
        const int kc   = (tid & 1) * 32;
        const float* src = Q + (size_t)(m0 + qrow) * DH + kc;
#pragma unroll
        for (int i = 0; i < 8; i++) {
            float4 v = *(const float4*)&src[i * 4];
            uint4 u = make_uint4(f2tf(v.x), f2tf(v.y), f2tf(v.z), f2tf(v.w));
            *(uint4*)&Qs[qrow * QS_STRIDE + kc + i * 4] = u;
        }
    }
    __syncthreads();

    // --- preload Q A-fragments: qf[8 k-chunks][4] ---
    uint32_t qf[8][4];
#pragma unroll
    for (int kc = 0; kc < 8; kc++) {
        qf[kc][0] = Qs[r0 * QS_STRIDE + kc * 8 + tg];
        qf[kc][1] = Qs[r1 * QS_STRIDE + kc * 8 + tg];
        qf[kc][2] = Qs[r0 * QS_STRIDE + kc * 8 + tg + 4];
        qf[kc][3] = Qs[r1 * QS_STRIDE + kc * 8 + tg + 4];
    }

    float rsum0 = 0.f, rsum1 = 0.f;
    float ctxacc[8][4];
#pragma unroll
    for (int dt = 0; dt < 8; dt++)
#pragma unroll
        for (int r = 0; r < 4; r++) ctxacc[dt][r] = 0.f;

    const unsigned char* mrow0 = mask + ((size_t)b * SEQ + m0 + r0) * SEQ;
    const unsigned char* mrow1 = mask + ((size_t)b * SEQ + m0 + r1) * SEQ;
    float* arow0 = attn + ((size_t)bh * SEQ + m0 + r0) * SEQ;
    float* arow1 = attn + ((size_t)bh * SEQ + m0 + r1) * SEQ;

    const int ld_key = tid >> 1;           // K loader: 0..127
    const int ld_kc  = (tid & 1) * 32;
    const int v_r    = tid >> 2;           // V loader: key-pair 0..63
    const int v_c    = (tid & 3) * 16;     // dim chunk

    for (int kt = 0; kt < 16; kt++) {
        // --- load K (tf32) and V (half2 key-pairs) tiles ---
        {
            const float* ksrc = K + (size_t)(kt * 128 + ld_key) * DH + ld_kc;
#pragma unroll
            for (int i = 0; i < 8; i++) {
                float4 kv = *(const float4*)&ksrc[i * 4];
                *(uint4*)&Ks[ld_key * QS_STRIDE + ld_kc + i * 4] =
                    make_uint4(f2tf(kv.x), f2tf(kv.y), f2tf(kv.z), f2tf(kv.w));
            }
            const float* v0src = V + (size_t)(kt * 128 + 2 * v_r) * DH + v_c;
            const float* v1src = v0src + DH;
#pragma unroll
            for (int i = 0; i < 4; i++) {
                float4 a = *(const float4*)&v0src[i * 4];   // key 2r
                float4 c = *(const float4*)&v1src[i * 4];   // key 2r+1
                uint4 u = make_uint4(pack_h2(a.x, c.x), pack_h2(a.y, c.y),
                                     pack_h2(a.z, c.z), pack_h2(a.w, c.w));
                *(uint4*)&Vhs[v_r * VH_STRIDE + v_c + i * 4] = u;
            }
        }
        __syncthreads();

        // --- S = Q K^T (tf32), 16 rows x 128 keys per warp ---
        float sacc[16][4];
#pragma unroll
        for (int nt = 0; nt < 16; nt++)
#pragma unroll
            for (int r = 0; r < 4; r++) sacc[nt][r] = 0.f;

#pragma unroll
        for (int kc = 0; kc < 8; kc++) {
#pragma unroll
            for (int nt = 0; nt < 16; nt++) {
                uint32_t bf[2];
                bf[0] = Ks[(nt * 8 + gr) * QS_STRIDE + kc * 8 + tg];
                bf[1] = Ks[(nt * 8 + gr) * QS_STRIDE + kc * 8 + tg + 4];
                mma_tf32(sacc[nt], qf[kc], bf);
            }
        }

        // --- scale, mask, exp, rowsum, write unnormalized p ---
        const int colb = kt * 128;
#pragma unroll
        for (int nt = 0; nt < 16; nt++) {
            const int col = colb + nt * 8 + 2 * tg;
            uchar2 mm0 = *(const uchar2*)&mrow0[col];
            uchar2 mm1 = *(const uchar2*)&mrow1[col];
            float s00 = mm0.x ? -1e9f : sacc[nt][0] * 0.125f;
            float s01 = mm0.y ? -1e9f : sacc[nt][1] * 0.125f;
            float s10 = mm1.x ? -1e9f : sacc[nt][2] * 0.125f;
            float s11 = mm1.y ? -1e9f : sacc[nt][3] * 0.125f;
            float p00 = __expf(s00), p01 = __expf(s01);
            float p10 = __expf(s10), p11 = __expf(s11);
            rsum0 += p00 + p01;
            rsum1 += p10 + p11;
            sacc[nt][0] = p00; sacc[nt][1] = p01;
            sacc[nt][2] = p10; sacc[nt][3] = p11;
            *(float2*)&arow0[col] = make_float2(p00, p01);
            *(float2*)&arow1[col] = make_float2(p10, p11);
        }

        // --- ctx += p @ V in fp16: C-frags -> A-frags in-thread, no shfl ---
        // Group g covers keys 16g..16g+15 (= S n8-tiles 2g, 2g+1).
        // A-frag (m16n8k16): a0=(row gr, k 2tg,2tg+1)=ntile 2g c0c1, etc.
        // B-frag: b0=Vhs[g*8+tg][d], b1=Vhs[g*8+4+tg][d] (half2 key pairs).
#pragma unroll
        for (int g = 0; g < 8; g++) {
            uint32_t pa[4];
            pa[0] = pack_h2(sacc[2 * g][0],     sacc[2 * g][1]);
            pa[1] = pack_h2(sacc[2 * g][2],     sacc[2 * g][3]);
            pa[2] = pack_h2(sacc[2 * g + 1][0], sacc[2 * g + 1][1]);
            pa[3] = pack_h2(sacc[2 * g + 1][2], sacc[2 * g + 1][3]);
#pragma unroll
            for (int dt = 0; dt < 8; dt++) {
                uint32_t vb[2];
                vb[0] = Vhs[(g * 8 + tg) * VH_STRIDE + dt * 8 + gr];
                vb[1] = Vhs[(g * 8 + 4 + tg) * VH_STRIDE + dt * 8 + gr];
                mma_f16(ctxacc[dt], pa, vb);
            }
        }
        __syncthreads();
    }

    // --- finalize: row sums (quad reduce), write sums, scale ctx ---
    rsum0 += __shfl_xor_sync(0xffffffffu, rsum0, 1);
    rsum0 += __shfl_xor_sync(0xffffffffu, rsum0, 2);
    rsum1 += __shfl_xor_sync(0xffffffffu, rsum1, 1);
    rsum1 += __shfl_xor_sync(0xffffffffu, rsum1, 2);
    if (tg == 0) {
        g_sums[(size_t)bh * SEQ + m0 + r0] = rsum0;
        g_sums[(size_t)bh * SEQ + m0 + r1] = rsum1;
    }
    const float inv0 = 1.0f / rsum0;
    const float inv1 = 1.0f / rsum1;

    float* crow0 = ctx + ((size_t)b * SEQ + m0 + r0) * DMOD + h * DH;
    float* crow1 = ctx + ((size_t)b * SEQ + m0 + r1) * DMOD + h * DH;
#pragma unroll
    for (int dt = 0; dt < 8; dt++) {
        const int d = dt * 8 + 2 * tg;
        *(float2*)&crow0[d] = make_float2(ctxacc[dt][0] * inv0, ctxacc[dt][1] * inv0);
        *(float2*)&crow1[d] = make_float2(ctxacc[dt][2] * inv1, ctxacc[dt][3] * inv1);
    }
}

// ---------------------------------------------------------------------------
// Kernel 3: scale attn rows by 1/rowsum (at DRAM roofline; unchanged).
// ---------------------------------------------------------------------------
__global__ __launch_bounds__(256) void scale_kernel(float* __restrict__ attn)
{
    const size_t row = blockIdx.x;
    const float inv = 1.0f / g_sums[row];
    float* p = attn + row * SEQ;
    const int tid = threadIdx.x;
    float4 v0 = *(float4*)&p[tid * 4];
    float4 v1 = *(float4*)&p[1024 + tid * 4];
    v0.x *= inv; v0.y *= inv; v0.z *= inv; v0.w *= inv;
    v1.x *= inv; v1.y *= inv; v1.z *= inv; v1.w *= inv;
    *(float4*)&p[tid * 4] = v0;
    *(float4*)&p[1024 + tid * 4] = v1;
}

// ---------------------------------------------------------------------------
// Launch. Output: [context (4,2048,1024) | attn (4,16,2048,2048)] fp32.
// Q/K/V for bh<58 staged in attn slices 58..63; bh>=58 in g_tail.
// ---------------------------------------------------------------------------
extern "C" void kernel_launch(void* const* d_in, const int* in_sizes, int n_in,
                              void* d_out, int out_size)
{
    (void)in_sizes; (void)n_in; (void)out_size;
    const float* q  = (const float*)d_in[0];
    const float* k  = (const float*)d_in[1];
    const float* v  = (const float*)d_in[2];
    const unsigned char* mask = (const unsigned char*)d_in[3];
    const float* wq = (const float*)d_in[4];
    const float* wk = (const float*)d_in[5];
    const float* wv = (const float*)d_in[6];
    const float* bq = (const float*)d_in[7];
    const float* bk = (const float*)d_in[8];
    const float* bv = (const float*)d_in[9];

    float* ctx   = (float*)d_out;
    float* attn  = (float*)d_out + (size_t)NB * SEQ * DMOD;
    float* stage = attn + (size_t)NSPLIT * SL;

    const int smem_bytes = SMEM_WORDS * 4;   // 88064 B
    cudaFuncSetAttribute(fused_attn_kernel,
                         cudaFuncAttributeMaxDynamicSharedMemorySize, smem_bytes);

    // 1) QKV projections into staging
    {
        dim3 grid(DMOD / 128, (NB * SEQ) / 128, 3);
        proj_kernel<<<grid, 256>>>(q, k, v, wq, wk, wv, bq, bk, bv, stage);
    }
    // 2) Phase A: fused attention for bh 0..57
    {
        dim3 grid(SEQ / 128, NSPLIT);
        fused_attn_kernel<<<grid, 256, smem_bytes>>>(mask, attn, ctx, stage, 0);
    }
    // 3) Phase B: fused attention for bh 58..63 (QKV in g_tail)
    {
        dim3 grid(SEQ / 128, BHN - NSPLIT);
        fused_attn_kernel<<<grid, 256, smem_bytes>>>(mask, attn, ctx, stage, NSPLIT);
    }
    // 4) Normalize the attn output
    scale_kernel<<<BHN * SEQ, 256>>>(attn);
}

// round 12
// speedup vs baseline: 1.5547x; 1.2391x over previous
#include <cuda_runtime.h>
#include <cuda_fp16.h>
#include <cstdint>

#define NB   4
#define NH   16
#define SEQ  2048
#define DMOD 1024
#define DH   64
#define BHN  (NB * NH)        // 64
#define SL   4194304          // floats per attn slice (2048*2048)
#define PBH  131072           // ELEMENTS per (bh) Q/K/V slab (2048*64), now half
#define NSPLIT 58             // bh 0..57 staged in d_out, 58..63 in g_tail

// Scratch: 6 tail (bh) Q/K/V slabs (4.7 MB, fp16) + row sums (0.5 MB).
static __device__ __half g_tail[18 * PBH];
static __device__ float g_sums[(size_t)BHN * SEQ];

// ---------------------------------------------------------------------------
// helpers
// ---------------------------------------------------------------------------
__device__ __forceinline__ uint32_t f2tf(float f) {
    uint32_t u;
    asm("cvt.rna.tf32.f32 %0, %1;" : "=r"(u) : "f"(f));
    return u;
}

__device__ __forceinline__ uint32_t pack_h2(float lo, float hi) {
    __half2 h = __floats2half2_rn(lo, hi);
    return *reinterpret_cast<uint32_t*>(&h);
}

__device__ __forceinline__ void mma_tf32(float* c, const uint32_t* a, const uint32_t* b) {
    asm volatile(
        "mma.sync.aligned.m16n8k8.row.col.f32.tf32.tf32.f32 "
        "{%0,%1,%2,%3}, {%4,%5,%6,%7}, {%8,%9}, {%0,%1,%2,%3};"
        : "+f"(c[0]), "+f"(c[1]), "+f"(c[2]), "+f"(c[3])
        : "r"(a[0]), "r"(a[1]), "r"(a[2]), "r"(a[3]), "r"(b[0]), "r"(b[1]));
}

__device__ __forceinline__ void mma_f16(float* c, const uint32_t* a, const uint32_t* b) {
    asm volatile(
        "mma.sync.aligned.m16n8k16.row.col.f32.f16.f16.f32 "
        "{%0,%1,%2,%3}, {%4,%5,%6,%7}, {%8,%9}, {%0,%1,%2,%3};"
        : "+f"(c[0]), "+f"(c[1]), "+f"(c[2]), "+f"(c[3])
        : "r"(a[0]), "r"(a[1]), "r"(a[2]), "r"(a[3]), "r"(b[0]), "r"(b[1]));
}

// ---------------------------------------------------------------------------
// Kernel 1: fused QKV projection via tf32 mma (validated GEMM core).
// Epilogue now writes Q/K/V slabs as fp16 (half2 stores, adjacent dims).
// ---------------------------------------------------------------------------
__global__ __launch_bounds__(256) void proj_kernel(
    const float* __restrict__ xq, const float* __restrict__ xk, const float* __restrict__ xv,
    const float* __restrict__ wq, const float* __restrict__ wk, const float* __restrict__ wv,
    const float* __restrict__ bq, const float* __restrict__ bk, const float* __restrict__ bv,
    __half* __restrict__ stage)
{
    const int which = blockIdx.z;
    const float* X  = (which == 0) ? xq : (which == 1) ? xk : xv;
    const float* W  = (which == 0) ? wq : (which == 1) ? wk : wv;
    const float* Bi = (which == 0) ? bq : (which == 1) ? bk : bv;

    __shared__ uint32_t As[16][136];
    __shared__ uint32_t Bs[16][136];

    const int tid  = threadIdx.x;
    const int warp = tid >> 5;
    const int lane = tid & 31;
    const int gr   = lane >> 2;
    const int tg   = lane & 3;

    const int m0 = blockIdx.y * 128;
    const int n0 = blockIdx.x * 128;
    const int warp_m = (warp >> 2) * 64;
    const int warp_n = (warp & 3) * 32;

    const int a_r = tid >> 1;
    const int a_kc = (tid & 1) * 8;
    const int b_kr = tid >> 4;
    const int b_nc = (tid & 15) * 8;

    float acc[4][4][4];
#pragma unroll
    for (int mt = 0; mt < 4; mt++)
#pragma unroll
        for (int nt = 0; nt < 4; nt++)
#pragma unroll
            for (int r = 0; r < 4; r++) acc[mt][nt][r] = 0.f;

    for (int k0 = 0; k0 < DMOD; k0 += 16) {
        float4 x0 = *(const float4*)&X[(size_t)(m0 + a_r) * DMOD + k0 + a_kc];
        float4 x1 = *(const float4*)&X[(size_t)(m0 + a_r) * DMOD + k0 + a_kc + 4];
        float4 w0 = *(const float4*)&W[(size_t)(k0 + b_kr) * DMOD + n0 + b_nc];
        float4 w1 = *(const float4*)&W[(size_t)(k0 + b_kr) * DMOD + n0 + b_nc + 4];
        __syncthreads();
        As[a_kc + 0][a_r] = f2tf(x0.x);
        As[a_kc + 1][a_r] = f2tf(x0.y);
        As[a_kc + 2][a_r] = f2tf(x0.z);
        As[a_kc + 3][a_r] = f2tf(x0.w);
        As[a_kc + 4][a_r] = f2tf(x1.x);
        As[a_kc + 5][a_r] = f2tf(x1.y);
        As[a_kc + 6][a_r] = f2tf(x1.z);
        As[a_kc + 7][a_r] = f2tf(x1.w);
        Bs[b_kr][b_nc + 0] = f2tf(w0.x);
        Bs[b_kr][b_nc + 1] = f2tf(w0.y);
        Bs[b_kr][b_nc + 2] = f2tf(w0.z);
        Bs[b_kr][b_nc + 3] = f2tf(w0.w);
        Bs[b_kr][b_nc + 4] = f2tf(w1.x);
        Bs[b_kr][b_nc + 5] = f2tf(w1.y);
        Bs[b_kr][b_nc + 6] = f2tf(w1.z);
        Bs[b_kr][b_nc + 7] = f2tf(w1.w);
        __syncthreads();

#pragma unroll
        for (int kk = 0; kk < 16; kk += 8) {
            uint32_t af[4][4], bf[4][2];
#pragma unroll
            for (int mt = 0; mt < 4; mt++) {
                const int mm = warp_m + mt * 16 + gr;
                af[mt][0] = As[kk + tg][mm];
                af[mt][1] = As[kk + tg][mm + 8];
                af[mt][2] = As[kk + tg + 4][mm];
                af[mt][3] = As[kk + tg + 4][mm + 8];
            }
#pragma unroll
            for (int nt = 0; nt < 4; nt++) {
                const int nn = warp_n + nt * 8 + gr;
                bf[nt][0] = Bs[kk + tg][nn];
                bf[nt][1] = Bs[kk + tg + 4][nn];
            }
#pragma unroll
            for (int mt = 0; mt < 4; mt++)
#pragma unroll
                for (int nt = 0; nt < 4; nt++)
                    mma_tf32(acc[mt][nt], af[mt], bf[nt]);
        }
    }

    const int h  = (n0 + warp_n) >> 6;
    const int bb = m0 >> 11;
    const int bh = bb * NH + h;
    const int d_base = ((n0 + warp_n) & 63);
    const int ss_base = (m0 & (SEQ - 1)) + warp_m;

    __half* dst = (bh < NSPLIT)
        ? stage + (size_t)which * ((size_t)NSPLIT * PBH) + (size_t)bh * PBH
        : g_tail + (size_t)which * (6 * PBH) + (size_t)(bh - NSPLIT) * PBH;

#pragma unroll
    for (int nt = 0; nt < 4; nt++) {
        const int ncol = n0 + warp_n + nt * 8 + 2 * tg;
        const float bias0 = Bi[ncol];
        const float bias1 = Bi[ncol + 1];
        const int d = d_base + nt * 8 + 2 * tg;
#pragma unroll
        for (int mt = 0; mt < 4; mt++) {
            const int s0 = ss_base + mt * 16 + gr;
            __half2 v0 = __floats2half2_rn(acc[mt][nt][0] + bias0, acc[mt][nt][1] + bias1);
            __half2 v1 = __floats2half2_rn(acc[mt][nt][2] + bias0, acc[mt][nt][3] + bias1);
            *(__half2*)&dst[(size_t)s0 * DH + d] = v0;
            *(__half2*)&dst[(size_t)(s0 + 8) * DH + d] = v1;
        }
    }
}

// ---------------------------------------------------------------------------
// Kernel 2: FUSED attention, all-fp16 tensor ops.
// Per block: one bh, 128 q-rows; warp w owns rows w*16..+15.
// Q fragments loaded directly from gmem (fp16). K tile copied raw to smem
// (half2 k-pairs = fragment layout). V interleaved into half2 key-pairs.
// S = QK^T fp16 m16n8k16 (fp32 acc) -> p = exp(S/8 masked) fp32 -> attn +
// rowsum; PV fp16 with in-thread C->A fragment reuse (no shuffles).
// Tile processed in two 64-key halves to cap live registers (2 blocks/SM).
// smem: Kh[128][36] + Vh[64][72] = 36.9 KB static.
// ---------------------------------------------------------------------------
#define KH_STRIDE 36
#define VH_STRIDE 72

__global__ __launch_bounds__(256, 2) void fused_attn_kernel(
    const unsigned char* __restrict__ mask, float* __restrict__ attn,
    float* __restrict__ ctx, const __half* __restrict__ stage, int bh0)
{
    __shared__ uint32_t Kh[128 * KH_STRIDE];
    __shared__ uint32_t Vh[64 * VH_STRIDE];

    const int bh = bh0 + blockIdx.y;
    const int m0 = blockIdx.x * 128;
    const int b = bh >> 4, h = bh & 15;

    const __half* Q = (bh < NSPLIT)
        ? stage + (size_t)bh * PBH
        : g_tail + (size_t)(bh - NSPLIT) * PBH;
    const __half* K = (bh < NSPLIT)
        ? stage + (size_t)NSPLIT * PBH + (size_t)bh * PBH
        : g_tail + (size_t)(6 * PBH) + (size_t)(bh - NSPLIT) * PBH;
    const __half* V = (bh < NSPLIT)
        ? stage + (size_t)(2 * NSPLIT) * PBH + (size_t)bh * PBH
        : g_tail + (size_t)(12 * PBH) + (size_t)(bh - NSPLIT) * PBH;

    const int tid  = threadIdx.x;
    const int warp = tid >> 5;
    const int lane = tid & 31;
    const int gr   = lane >> 2;
    const int tg   = lane & 3;

    const int r0 = warp * 16 + gr;
    const int r1 = r0 + 8;

    // --- Q A-fragments straight from gmem: qf[4 k-chunks][4] (fp16 pairs) ---
    uint32_t qf[4][4];
#pragma unroll
    for (int kc = 0; kc < 4; kc++) {
        qf[kc][0] = *(const uint32_t*)&Q[(size_t)(m0 + r0) * DH + (kc * 8 + tg) * 2];
        qf[kc][1] = *(const uint32_t*)&Q[(size_t)(m0 + r1) * DH + (kc * 8 + tg) * 2];
        qf[kc][2] = *(const uint32_t*)&Q[(size_t)(m0 + r0) * DH + (kc * 8 + tg + 4) * 2];
        qf[kc][3] = *(const uint32_t*)&Q[(size_t)(m0 + r1) * DH + (kc * 8 + tg + 4) * 2];
    }

    float rsum0 = 0.f, rsum1 = 0.f;
    float ctxacc[8][4];
#pragma unroll
    for (int dt = 0; dt < 8; dt++)
#pragma unroll
        for (int r = 0; r < 4; r++) ctxacc[dt][r] = 0.f;

    const unsigned char* mrow0 = mask + ((size_t)b * SEQ + m0 + r0) * SEQ;
    const unsigned char* mrow1 = mask + ((size_t)b * SEQ + m0 + r1) * SEQ;
    float* arow0 = attn + ((size_t)bh * SEQ + m0 + r0) * SEQ;
    float* arow1 = attn + ((size_t)bh * SEQ + m0 + r1) * SEQ;

    const int ld_key = tid >> 1;           // K loader: key 0..127
    const int ld_pc  = (tid & 1) * 16;     // pair-chunk (uint32 index)
    const int v_r    = tid >> 2;           // V loader: key-pair 0..63
    const int v_cw   = (tid & 3) * 8;      // dim-word chunk (8 uint32 = 16 halves)

    for (int kt = 0; kt < 16; kt++) {
        // --- K tile: raw copy (gmem half2 pairs == fragment layout) ---
        {
            const uint32_t* ksrc =
                (const uint32_t*)(K + (size_t)(kt * 128 + ld_key) * DH) + ld_pc;
#pragma unroll
            for (int i = 0; i < 4; i++) {
                uint4 u = *(const uint4*)&ksrc[i * 4];
                *(uint4*)&Kh[ld_key * KH_STRIDE + ld_pc + i * 4] = u;
            }
            // --- V tile: interleave two key rows into half2 key-pairs ---
            const uint32_t* v0w =
                (const uint32_t*)(V + (size_t)(kt * 128 + 2 * v_r) * DH) + v_cw;
            const uint32_t* v1w = v0w + DH / 2;
            uint32_t out[16];
#pragma unroll
            for (int j = 0; j < 8; j++) {
                uint32_t a = v0w[j], c = v1w[j];
                out[2 * j]     = __byte_perm(a, c, 0x5410);   // lo halves
                out[2 * j + 1] = __byte_perm(a, c, 0x7632);   // hi halves
            }
#pragma unroll
            for (int i = 0; i < 4; i++)
                *(uint4*)&Vh[v_r * VH_STRIDE + v_cw * 2 + i * 4] = *(uint4*)&out[i * 4];
        }
        __syncthreads();

#pragma unroll
        for (int hk = 0; hk < 2; hk++) {
            const int kbase = hk * 64;

            // --- S = Q K^T (fp16), 16 rows x 64 keys ---
            float sacc[8][4];
#pragma unroll
            for (int nt = 0; nt < 8; nt++)
#pragma unroll
                for (int r = 0; r < 4; r++) sacc[nt][r] = 0.f;

#pragma unroll
            for (int kc = 0; kc < 4; kc++) {
#pragma unroll
                for (int nt = 0; nt < 8; nt++) {
                    uint32_t bf[2];
                    bf[0] = Kh[(kbase + nt * 8 + gr) * KH_STRIDE + kc * 8 + tg];
                    bf[1] = Kh[(kbase + nt * 8 + gr) * KH_STRIDE + kc * 8 + tg + 4];
                    mma_f16(sacc[nt], qf[kc], bf);
                }
            }

            // --- scale, mask, exp, rowsum, write unnormalized p ---
            const int colb = kt * 128 + kbase;
#pragma unroll
            for (int nt = 0; nt < 8; nt++) {
                const int col = colb + nt * 8 + 2 * tg;
                uchar2 mm0 = *(const uchar2*)&mrow0[col];
                uchar2 mm1 = *(const uchar2*)&mrow1[col];
                float s00 = mm0.x ? -1e9f : sacc[nt][0] * 0.125f;
                float s01 = mm0.y ? -1e9f : sacc[nt][1] * 0.125f;
                float s10 = mm1.x ? -1e9f : sacc[nt][2] * 0.125f;
                float s11 = mm1.y ? -1e9f : sacc[nt][3] * 0.125f;
                float p00 = __expf(s00), p01 = __expf(s01);
                float p10 = __expf(s10), p11 = __expf(s11);
                rsum0 += p00 + p01;
                rsum1 += p10 + p11;
                sacc[nt][0] = p00; sacc[nt][1] = p01;
                sacc[nt][2] = p10; sacc[nt][3] = p11;
                *(float2*)&arow0[col] = make_float2(p00, p01);
                *(float2*)&arow1[col] = make_float2(p10, p11);
            }

            // --- ctx += p @ V (fp16, in-thread C->A fragment reuse) ---
#pragma unroll
            for (int g = 0; g < 4; g++) {
                uint32_t pa[4];
                pa[0] = pack_h2(sacc[2 * g][0],     sacc[2 * g][1]);
                pa[1] = pack_h2(sacc[2 * g][2],     sacc[2 * g][3]);
                pa[2] = pack_h2(sacc[2 * g + 1][0], sacc[2 * g + 1][1]);
                pa[3] = pack_h2(sacc[2 * g + 1][2], sacc[2 * g + 1][3]);
#pragma unroll
                for (int dt = 0; dt < 8; dt++) {
                    uint32_t vb[2];
                    vb[0] = Vh[(hk * 32 + g * 8 + tg) * VH_STRIDE + dt * 8 + gr];
                    vb[1] = Vh[(hk * 32 + g * 8 + tg + 4) * VH_STRIDE + dt * 8 + gr];
                    mma_f16(ctxacc[dt], pa, vb);
                }
            }
        }
        __syncthreads();
    }

    // --- finalize: row sums (quad reduce), write sums, scale ctx ---
    rsum0 += __shfl_xor_sync(0xffffffffu, rsum0, 1);
    rsum0 += __shfl_xor_sync(0xffffffffu, rsum0, 2);
    rsum1 += __shfl_xor_sync(0xffffffffu, rsum1, 1);
    rsum1 += __shfl_xor_sync(0xffffffffu, rsum1, 2);
    if (tg == 0) {
        g_sums[(size_t)bh * SEQ + m0 + r0] = rsum0;
        g_sums[(size_t)bh * SEQ + m0 + r1] = rsum1;
    }
    const float inv0 = 1.0f / rsum0;
    const float inv1 = 1.0f / rsum1;

    float* crow0 = ctx + ((size_t)b * SEQ + m0 + r0) * DMOD + h * DH;
    float* crow1 = ctx + ((size_t)b * SEQ + m0 + r1) * DMOD + h * DH;
#pragma unroll
    for (int dt = 0; dt < 8; dt++) {
        const int d = dt * 8 + 2 * tg;
        *(float2*)&crow0[d] = make_float2(ctxacc[dt][0] * inv0, ctxacc[dt][1] * inv0);
        *(float2*)&crow1[d] = make_float2(ctxacc[dt][2] * inv1, ctxacc[dt][3] * inv1);
    }
}

// ---------------------------------------------------------------------------
// Kernel 3: scale attn rows by 1/rowsum (at DRAM roofline; unchanged).
// ---------------------------------------------------------------------------
__global__ __launch_bounds__(256) void scale_kernel(float* __restrict__ attn)
{
    const size_t row = blockIdx.x;
    const float inv = 1.0f / g_sums[row];
    float* p = attn + row * SEQ;
    const int tid = threadIdx.x;
    float4 v0 = *(float4*)&p[tid * 4];
    float4 v1 = *(float4*)&p[1024 + tid * 4];
    v0.x *= inv; v0.y *= inv; v0.z *= inv; v0.w *= inv;
    v1.x *= inv; v1.y *= inv; v1.z *= inv; v1.w *= inv;
    *(float4*)&p[tid * 4] = v0;
    *(float4*)&p[1024 + tid * 4] = v1;
}

// ---------------------------------------------------------------------------
// Launch. Output: [context (4,2048,1024) | attn (4,16,2048,2048)] fp32.
// Q/K/V (fp16) for bh<58 staged in attn slices 58..63; bh>=58 in g_tail.
// ---------------------------------------------------------------------------
extern "C" void kernel_launch(void* const* d_in, const int* in_sizes, int n_in,
                              void* d_out, int out_size)
{
    (void)in_sizes; (void)n_in; (void)out_size;
    const float* q  = (const float*)d_in[0];
    const float* k  = (const float*)d_in[1];
    const float* v  = (const float*)d_in[2];
    const unsigned char* mask = (const unsigned char*)d_in[3];
    const float* wq = (const float*)d_in[4];
    const float* wk = (const float*)d_in[5];
    const float* wv = (const float*)d_in[6];
    const float* bq = (const float*)d_in[7];
    const float* bk = (const float*)d_in[8];
    const float* bv = (const float*)d_in[9];

    float* ctx   = (float*)d_out;
    float* attn  = (float*)d_out + (size_t)NB * SEQ * DMOD;
    __half* stage = (__half*)(attn + (size_t)NSPLIT * SL);   // slices 58..63

    // 1) QKV projections into fp16 staging
    {
        dim3 grid(DMOD / 128, (NB * SEQ) / 128, 3);
        proj_kernel<<<grid, 256>>>(q, k, v, wq, wk, wv, bq, bk, bv, stage);
    }
    // 2) Phase A: fused attention for bh 0..57
    {
        dim3 grid(SEQ / 128, NSPLIT);
        fused_attn_kernel<<<grid, 256>>>(mask, attn, ctx, stage, 0);
    }
    // 3) Phase B: fused attention for bh 58..63 (QKV in g_tail)
    {
        dim3 grid(SEQ / 128, BHN - NSPLIT);
        fused_attn_kernel<<<grid, 256>>>(mask, attn, ctx, stage, NSPLIT);
    }
    // 4) Normalize the attn output
    scale_kernel<<<BHN * SEQ, 256>>>(attn);
}

// round 13
// speedup vs baseline: 1.6694x; 1.0738x over previous
#include <cuda_runtime.h>
#include <cuda_fp16.h>
#include <cstdint>

#define NB   4
#define NH   16
#define SEQ  2048
#define DMOD 1024
#define DH   64
#define BHN  (NB * NH)        // 64
#define SL   4194304          // floats per attn slice (2048*2048)
#define PBH  131072           // ELEMENTS per (bh) Q/K/V slab (2048*64), fp16
#define NSPLIT 58             // bh 0..57 staged in d_out, 58..63 in g_tail

// Scratch: 6 tail (bh) Q/K/V slabs (4.7 MB, fp16) + row sums (0.5 MB).
static __device__ __half g_tail[18 * PBH];
static __device__ float g_sums[(size_t)BHN * SEQ];

// ---------------------------------------------------------------------------
// helpers
// ---------------------------------------------------------------------------
__device__ __forceinline__ uint32_t f2tf(float f) {
    uint32_t u;
    asm("cvt.rna.tf32.f32 %0, %1;" : "=r"(u) : "f"(f));
    return u;
}

__device__ __forceinline__ uint32_t pack_h2(float lo, float hi) {
    __half2 h = __floats2half2_rn(lo, hi);
    return *reinterpret_cast<uint32_t*>(&h);
}

__device__ __forceinline__ void mma_tf32(float* c, const uint32_t* a, const uint32_t* b) {
    asm volatile(
        "mma.sync.aligned.m16n8k8.row.col.f32.tf32.tf32.f32 "
        "{%0,%1,%2,%3}, {%4,%5,%6,%7}, {%8,%9}, {%0,%1,%2,%3};"
        : "+f"(c[0]), "+f"(c[1]), "+f"(c[2]), "+f"(c[3])
        : "r"(a[0]), "r"(a[1]), "r"(a[2]), "r"(a[3]), "r"(b[0]), "r"(b[1]));
}

__device__ __forceinline__ void mma_f16(float* c, const uint32_t* a, const uint32_t* b) {
    asm volatile(
        "mma.sync.aligned.m16n8k16.row.col.f32.f16.f16.f32 "
        "{%0,%1,%2,%3}, {%4,%5,%6,%7}, {%8,%9}, {%0,%1,%2,%3};"
        : "+f"(c[0]), "+f"(c[1]), "+f"(c[2]), "+f"(c[3])
        : "r"(a[0]), "r"(a[1]), "r"(a[2]), "r"(a[3]), "r"(b[0]), "r"(b[1]));
}

__device__ __forceinline__ void cp16(uint32_t smem_addr, const void* g) {
    asm volatile("cp.async.ca.shared.global [%0], [%1], 16;"
                 :: "r"(smem_addr), "l"(g));
}
#define CP_COMMIT() asm volatile("cp.async.commit_group;")
#define CP_WAIT0()  asm volatile("cp.async.wait_group 0;")

// ---------------------------------------------------------------------------
// Kernel 1: fused QKV projection via tf32 mma (validated GEMM core).
// Q/K written as fp16 (s,d) rows; V written PRE-INTERLEAVED as half2
// key-pairs: slab index = (s>>1)*2*DH + 2*d + (s&1).
// ---------------------------------------------------------------------------
__global__ __launch_bounds__(256) void proj_kernel(
    const float* __restrict__ xq, const float* __restrict__ xk, const float* __restrict__ xv,
    const float* __restrict__ wq, const float* __restrict__ wk, const float* __restrict__ wv,
    const float* __restrict__ bq, const float* __restrict__ bk, const float* __restrict__ bv,
    __half* __restrict__ stage)
{
    const int which = blockIdx.z;
    const float* X  = (which == 0) ? xq : (which == 1) ? xk : xv;
    const float* W  = (which == 0) ? wq : (which == 1) ? wk : wv;
    const float* Bi = (which == 0) ? bq : (which == 1) ? bk : bv;

    __shared__ uint32_t As[16][136];
    __shared__ uint32_t Bs[16][136];

    const int tid  = threadIdx.x;
    const int warp = tid >> 5;
    const int lane = tid & 31;
    const int gr   = lane >> 2;
    const int tg   = lane & 3;

    const int m0 = blockIdx.y * 128;
    const int n0 = blockIdx.x * 128;
    const int warp_m = (warp >> 2) * 64;
    const int warp_n = (warp & 3) * 32;

    const int a_r = tid >> 1;
    const int a_kc = (tid & 1) * 8;
    const int b_kr = tid >> 4;
    const int b_nc = (tid & 15) * 8;

    float acc[4][4][4];
#pragma unroll
    for (int mt = 0; mt < 4; mt++)
#pragma unroll
        for (int nt = 0; nt < 4; nt++)
#pragma unroll
            for (int r = 0; r < 4; r++) acc[mt][nt][r] = 0.f;

    for (int k0 = 0; k0 < DMOD; k0 += 16) {
        float4 x0 = *(const float4*)&X[(size_t)(m0 + a_r) * DMOD + k0 + a_kc];
        float4 x1 = *(const float4*)&X[(size_t)(m0 + a_r) * DMOD + k0 + a_kc + 4];
        float4 w0 = *(const float4*)&W[(size_t)(k0 + b_kr) * DMOD + n0 + b_nc];
        float4 w1 = *(const float4*)&W[(size_t)(k0 + b_kr) * DMOD + n0 + b_nc + 4];
        __syncthreads();
        As[a_kc + 0][a_r] = f2tf(x0.x);
        As[a_kc + 1][a_r] = f2tf(x0.y);
        As[a_kc + 2][a_r] = f2tf(x0.z);
        As[a_kc + 3][a_r] = f2tf(x0.w);
        As[a_kc + 4][a_r] = f2tf(x1.x);
        As[a_kc + 5][a_r] = f2tf(x1.y);
        As[a_kc + 6][a_r] = f2tf(x1.z);
        As[a_kc + 7][a_r] = f2tf(x1.w);
        Bs[b_kr][b_nc + 0] = f2tf(w0.x);
        Bs[b_kr][b_nc + 1] = f2tf(w0.y);
        Bs[b_kr][b_nc + 2] = f2tf(w0.z);
        Bs[b_kr][b_nc + 3] = f2tf(w0.w);
        Bs[b_kr][b_nc + 4] = f2tf(w1.x);
        Bs[b_kr][b_nc + 5] = f2tf(w1.y);
        Bs[b_kr][b_nc + 6] = f2tf(w1.z);
        Bs[b_kr][b_nc + 7] = f2tf(w1.w);
        __syncthreads();

#pragma unroll
        for (int kk = 0; kk < 16; kk += 8) {
            uint32_t af[4][4], bf[4][2];
#pragma unroll
            for (int mt = 0; mt < 4; mt++) {
                const int mm = warp_m + mt * 16 + gr;
                af[mt][0] = As[kk + tg][mm];
                af[mt][1] = As[kk + tg][mm + 8];
                af[mt][2] = As[kk + tg + 4][mm];
                af[mt][3] = As[kk + tg + 4][mm + 8];
            }
#pragma unroll
            for (int nt = 0; nt < 4; nt++) {
                const int nn = warp_n + nt * 8 + gr;
                bf[nt][0] = Bs[kk + tg][nn];
                bf[nt][1] = Bs[kk + tg + 4][nn];
            }
#pragma unroll
            for (int mt = 0; mt < 4; mt++)
#pragma unroll
                for (int nt = 0; nt < 4; nt++)
                    mma_tf32(acc[mt][nt], af[mt], bf[nt]);
        }
    }

    const int h  = (n0 + warp_n) >> 6;
    const int bb = m0 >> 11;
    const int bh = bb * NH + h;
    const int d_base = ((n0 + warp_n) & 63);
    const int ss_base = (m0 & (SEQ - 1)) + warp_m;

    __half* dst = (bh < NSPLIT)
        ? stage + (size_t)which * ((size_t)NSPLIT * PBH) + (size_t)bh * PBH
        : g_tail + (size_t)which * (6 * PBH) + (size_t)(bh - NSPLIT) * PBH;

#pragma unroll
    for (int nt = 0; nt < 4; nt++) {
        const int ncol = n0 + warp_n + nt * 8 + 2 * tg;
        const float bias0 = Bi[ncol];
        const float bias1 = Bi[ncol + 1];
        const int d = d_base + nt * 8 + 2 * tg;
#pragma unroll
        for (int mt = 0; mt < 4; mt++) {
            const int s0 = ss_base + mt * 16 + gr;
            const int s1 = s0 + 8;
            if (which == 2) {
                // V: interleaved half2 key-pair layout
                dst[(size_t)(s0 >> 1) * (2 * DH) + 2 * d + (s0 & 1)] =
                    __float2half(acc[mt][nt][0] + bias0);
                dst[(size_t)(s0 >> 1) * (2 * DH) + 2 * (d + 1) + (s0 & 1)] =
                    __float2half(acc[mt][nt][1] + bias1);
                dst[(size_t)(s1 >> 1) * (2 * DH) + 2 * d + (s1 & 1)] =
                    __float2half(acc[mt][nt][2] + bias0);
                dst[(size_t)(s1 >> 1) * (2 * DH) + 2 * (d + 1) + (s1 & 1)] =
                    __float2half(acc[mt][nt][3] + bias1);
            } else {
                __half2 v0 = __floats2half2_rn(acc[mt][nt][0] + bias0, acc[mt][nt][1] + bias1);
                __half2 v1 = __floats2half2_rn(acc[mt][nt][2] + bias0, acc[mt][nt][3] + bias1);
                *(__half2*)&dst[(size_t)s0 * DH + d] = v0;
                *(__half2*)&dst[(size_t)s1 * DH + d] = v1;
            }
        }
    }
}

// ---------------------------------------------------------------------------
// Kernel 2: FUSED attention, all-fp16 tensor ops + cp.async double buffering.
// Per block: one bh, 128 q-rows; warp w owns rows w*16..+15.
// K tile: raw fp16 rows (fragment layout). V tile: pre-interleaved key-pairs.
// Mask tile staged in smem. All tiles double-buffered via cp.async.
// smem layout (words), per buffer: K[128*36] | V[64*72] | M[128*36]
// ---------------------------------------------------------------------------
#define KW 36                       // K row stride (words), 144B
#define VW 72                       // V row stride (words), 288B
#define MW 36                       // mask row stride (words), 144B
#define KBUF (128 * KW)             // 4608 words
#define VBUF (64 * VW)              // 4608 words
#define MBUF (128 * MW)             // 4608 words
#define TBUF (KBUF + VBUF + MBUF)   // 13824 words per buffer
#define SMEM_WORDS (2 * TBUF)       // 27648 words = 110592 B

__global__ __launch_bounds__(256, 2) void fused_attn_kernel(
    const unsigned char* __restrict__ mask, float* __restrict__ attn,
    float* __restrict__ ctx, const __half* __restrict__ stage, int bh0)
{
    extern __shared__ uint32_t smem[];

    const int bh = bh0 + blockIdx.y;
    const int m0 = blockIdx.x * 128;
    const int b = bh >> 4, h = bh & 15;

    const __half* Q = (bh < NSPLIT)
        ? stage + (size_t)bh * PBH
        : g_tail + (size_t)(bh - NSPLIT) * PBH;
    const __half* K = (bh < NSPLIT)
        ? stage + (size_t)NSPLIT * PBH + (size_t)bh * PBH
        : g_tail + (size_t)(6 * PBH) + (size_t)(bh - NSPLIT) * PBH;
    const __half* V = (bh < NSPLIT)
        ? stage + (size_t)(2 * NSPLIT) * PBH + (size_t)bh * PBH
        : g_tail + (size_t)(12 * PBH) + (size_t)(bh - NSPLIT) * PBH;

    const int tid  = threadIdx.x;
    const int warp = tid >> 5;
    const int lane = tid & 31;
    const int gr   = lane >> 2;
    const int tg   = lane & 3;

    const int r0 = warp * 16 + gr;
    const int r1 = r0 + 8;

    const uint32_t smem_base = (uint32_t)__cvta_generic_to_shared(smem);

    // --- Q A-fragments straight from gmem: qf[4 k-chunks][4] (fp16 pairs) ---
    uint32_t qf[4][4];
#pragma unroll
    for (int kc = 0; kc < 4; kc++) {
        qf[kc][0] = *(const uint32_t*)&Q[(size_t)(m0 + r0) * DH + (kc * 8 + tg) * 2];
        qf[kc][1] = *(const uint32_t*)&Q[(size_t)(m0 + r1) * DH + (kc * 8 + tg) * 2];
        qf[kc][2] = *(const uint32_t*)&Q[(size_t)(m0 + r0) * DH + (kc * 8 + tg + 4) * 2];
        qf[kc][3] = *(const uint32_t*)&Q[(size_t)(m0 + r1) * DH + (kc * 8 + tg + 4) * 2];
    }

    float rsum0 = 0.f, rsum1 = 0.f;
    float ctxacc[8][4];
#pragma unroll
    for (int dt = 0; dt < 8; dt++)
#pragma unroll
        for (int r = 0; r < 4; r++) ctxacc[dt][r] = 0.f;

    float* arow0 = attn + ((size_t)bh * SEQ + m0 + r0) * SEQ;
    float* arow1 = attn + ((size_t)bh * SEQ + m0 + r1) * SEQ;

    // loader indices
    const int k_row = tid >> 1;            // 0..127
    const int k_cw  = (tid & 1) * 16;      // word offset in K row
    const int v_row = tid >> 2;            // pair 0..63
    const int v_cw  = (tid & 3) * 16;      // word offset in V row
    const int m_row = tid >> 1;            // 0..127
    const int m_cb  = (tid & 1) * 64;      // byte offset in mask row

    const unsigned char* mask_base = mask + ((size_t)b * SEQ + m0) * SEQ;

    // tile loader: issues 12 cp.async.128 + commit
    auto load_tile = [&](int kt, int buf) {
        const uint32_t boff = smem_base + buf * (TBUF * 4);
        // K: 128 rows x 64 halves
        {
            const __half* src = K + (size_t)(kt * 128 + k_row) * DH + k_cw * 2;
            uint32_t dst = boff + (k_row * KW + k_cw) * 4;
            cp16(dst, src);
            cp16(dst + 16, src + 8);
            cp16(dst + 32, src + 16);
            cp16(dst + 48, src + 24);
        }
        // V (interleaved pairs): 64 rows x 128 halves
        {
            const __half* src = V + (size_t)(kt * 64 + v_row) * (2 * DH) + v_cw * 2;
            uint32_t dst = boff + (KBUF + v_row * VW + v_cw) * 4;
            cp16(dst, src);
            cp16(dst + 16, src + 8);
            cp16(dst + 32, src + 16);
            cp16(dst + 48, src + 24);
        }
        // mask: 128 rows x 128 bytes
        {
            const unsigned char* src = mask_base + (size_t)m_row * SEQ + kt * 128 + m_cb;
            uint32_t dst = boff + (KBUF + VBUF + m_row * MW) * 4 + m_cb;
            cp16(dst, src);
            cp16(dst + 16, src + 16);
            cp16(dst + 32, src + 32);
            cp16(dst + 48, src + 48);
        }
        CP_COMMIT();
    };

    load_tile(0, 0);
    int buf = 0;

    for (int kt = 0; kt < 16; kt++) {
        CP_WAIT0();
        __syncthreads();
        if (kt < 15) load_tile(kt + 1, buf ^ 1);

        const uint32_t* Kh = smem + buf * TBUF;
        const uint32_t* Vh = Kh + KBUF;
        const unsigned char* Mh = (const unsigned char*)(Vh + VBUF);

#pragma unroll
        for (int hk = 0; hk < 2; hk++) {
            const int kbase = hk * 64;

            // --- S = Q K^T (fp16), 16 rows x 64 keys ---
            float sacc[8][4];
#pragma unroll
            for (int nt = 0; nt < 8; nt++)
#pragma unroll
                for (int r = 0; r < 4; r++) sacc[nt][r] = 0.f;

#pragma unroll
            for (int kc = 0; kc < 4; kc++) {
#pragma unroll
                for (int nt = 0; nt < 8; nt++) {
                    uint32_t bf[2];
                    bf[0] = Kh[(kbase + nt * 8 + gr) * KW + kc * 8 + tg];
                    bf[1] = Kh[(kbase + nt * 8 + gr) * KW + kc * 8 + tg + 4];
                    mma_f16(sacc[nt], qf[kc], bf);
                }
            }

            // --- scale, mask (from smem), exp, rowsum, write p ---
            const int colb = kt * 128 + kbase;
#pragma unroll
            for (int nt = 0; nt < 8; nt++) {
                const int lcol = kbase + nt * 8 + 2 * tg;
                const int col  = colb + nt * 8 + 2 * tg;
                uchar2 mm0 = *(const uchar2*)&Mh[(size_t)r0 * (MW * 4) + lcol];
                uchar2 mm1 = *(const uchar2*)&Mh[(size_t)r1 * (MW * 4) + lcol];
                float s00 = mm0.x ? -1e9f : sacc[nt][0] * 0.125f;
                float s01 = mm0.y ? -1e9f : sacc[nt][1] * 0.125f;
                float s10 = mm1.x ? -1e9f : sacc[nt][2] * 0.125f;
                float s11 = mm1.y ? -1e9f : sacc[nt][3] * 0.125f;
                float p00 = __expf(s00), p01 = __expf(s01);
                float p10 = __expf(s10), p11 = __expf(s11);
                rsum0 += p00 + p01;
                rsum1 += p10 + p11;
                sacc[nt][0] = p00; sacc[nt][1] = p01;
                sacc[nt][2] = p10; sacc[nt][3] = p11;
                *(float2*)&arow0[col] = make_float2(p00, p01);
                *(float2*)&arow1[col] = make_float2(p10, p11);
            }

            // --- ctx += p @ V (fp16, in-thread C->A fragment reuse) ---
#pragma unroll
            for (int g = 0; g < 4; g++) {
                uint32_t pa[4];
                pa[0] = pack_h2(sacc[2 * g][0],     sacc[2 * g][1]);
                pa[1] = pack_h2(sacc[2 * g][2],     sacc[2 * g][3]);
                pa[2] = pack_h2(sacc[2 * g + 1][0], sacc[2 * g + 1][1]);
                pa[3] = pack_h2(sacc[2 * g + 1][2], sacc[2 * g + 1][3]);
#pragma unroll
                for (int dt = 0; dt < 8; dt++) {
                    uint32_t vb[2];
                    vb[0] = Vh[(hk * 32 + g * 8 + tg) * VW + dt * 8 + gr];
                    vb[1] = Vh[(hk * 32 + g * 8 + tg + 4) * VW + dt * 8 + gr];
                    mma_f16(ctxacc[dt], pa, vb);
                }
            }
        }
        __syncthreads();
        buf ^= 1;
    }

    // --- finalize: row sums (quad reduce), write sums, scale ctx ---
    rsum0 += __shfl_xor_sync(0xffffffffu, rsum0, 1);
    rsum0 += __shfl_xor_sync(0xffffffffu, rsum0, 2);
    rsum1 += __shfl_xor_sync(0xffffffffu, rsum1, 1);
    rsum1 += __shfl_xor_sync(0xffffffffu, rsum1, 2);
    if (tg == 0) {
        g_sums[(size_t)bh * SEQ + m0 + r0] = rsum0;
        g_sums[(size_t)bh * SEQ + m0 + r1] = rsum1;
    }
    const float inv0 = 1.0f / rsum0;
    const float inv1 = 1.0f / rsum1;

    float* crow0 = ctx + ((size_t)b * SEQ + m0 + r0) * DMOD + h * DH;
    float* crow1 = ctx + ((size_t)b * SEQ + m0 + r1) * DMOD + h * DH;
#pragma unroll
    for (int dt = 0; dt < 8; dt++) {
        const int d = dt * 8 + 2 * tg;
        *(float2*)&crow0[d] = make_float2(ctxacc[dt][0] * inv0, ctxacc[dt][1] * inv0);
        *(float2*)&crow1[d] = make_float2(ctxacc[dt][2] * inv1, ctxacc[dt][3] * inv1);
    }
}

// ---------------------------------------------------------------------------
// Kernel 3: scale attn rows by 1/rowsum (at DRAM roofline; unchanged).
// ---------------------------------------------------------------------------
__global__ __launch_bounds__(256) void scale_kernel(float* __restrict__ attn)
{
    const size_t row = blockIdx.x;
    const float inv = 1.0f / g_sums[row];
    float* p = attn + row * SEQ;
    const int tid = threadIdx.x;
    float4 v0 = *(float4*)&p[tid * 4];
    float4 v1 = *(float4*)&p[1024 + tid * 4];
    v0.x *= inv; v0.y *= inv; v0.z *= inv; v0.w *= inv;
    v1.x *= inv; v1.y *= inv; v1.z *= inv; v1.w *= inv;
    *(float4*)&p[tid * 4] = v0;
    *(float4*)&p[1024 + tid * 4] = v1;
}

// ---------------------------------------------------------------------------
// Launch. Output: [context (4,2048,1024) | attn (4,16,2048,2048)] fp32.
// Q/K/V (fp16) for bh<58 staged in attn slices 58..63; bh>=58 in g_tail.
// ---------------------------------------------------------------------------
extern "C" void kernel_launch(void* const* d_in, const int* in_sizes, int n_in,
                              void* d_out, int out_size)
{
    (void)in_sizes; (void)n_in; (void)out_size;
    const float* q  = (const float*)d_in[0];
    const float* k  = (const float*)d_in[1];
    const float* v  = (const float*)d_in[2];
    const unsigned char* mask = (const unsigned char*)d_in[3];
    const float* wq = (const float*)d_in[4];
    const float* wk = (const float*)d_in[5];
    const float* wv = (const float*)d_in[6];
    const float* bq = (const float*)d_in[7];
    const float* bk = (const float*)d_in[8];
    const float* bv = (const float*)d_in[9];

    float* ctx   = (float*)d_out;
    float* attn  = (float*)d_out + (size_t)NB * SEQ * DMOD;
    __half* stage = (__half*)(attn + (size_t)NSPLIT * SL);   // slices 58..63

    const int smem_bytes = SMEM_WORDS * 4;   // 110592 B
    cudaFuncSetAttribute(fused_attn_kernel,
                         cudaFuncAttributeMaxDynamicSharedMemorySize, smem_bytes);

    // 1) QKV projections into fp16 staging (V interleaved)
    {
        dim3 grid(DMOD / 128, (NB * SEQ) / 128, 3);
        proj_kernel<<<grid, 256>>>(q, k, v, wq, wk, wv, bq, bk, bv, stage);
    }
    // 2) Phase A: fused attention for bh 0..57
    {
        dim3 grid(SEQ / 128, NSPLIT);
        fused_attn_kernel<<<grid, 256, smem_bytes>>>(mask, attn, ctx, stage, 0);
    }
    // 3) Phase B: fused attention for bh 58..63 (QKV in g_tail)
    {
        dim3 grid(SEQ / 128, BHN - NSPLIT);
        fused_attn_kernel<<<grid, 256, smem_bytes>>>(mask, attn, ctx, stage, NSPLIT);
    }
    // 4) Normalize the attn output
    scale_kernel<<<BHN * SEQ, 256>>>(attn);
}